// round 1
// baseline (speedup 1.0000x reference)
#include <cuda_runtime.h>
#include <cuda_bf16.h>
#include <cstdint>

// ---------------------------------------------------------------------------
// APD2Net: the "graph" ops are dense ops in disguise.
//   graph_conv  == 3x3 SAME conv (zero pad), weights (O, C, 9) with k = ky*3+kx
//   graph_pool  == 2x2 spatial maxpool
// We run everything in NCHW. Output of last conv is directly the NCHW result.
//
// Pipeline (B=2):
//   conv 3->64   @384    conv 64->64  @384    pool ->192
//   conv 64->128 @192    conv 128->128 @192   pool ->96
//   conv 128->256 @96    conv 256->256 @96 x2 pool ->48
//   conv 256->512 @48    conv 512->512 @48 x2 -> d_out (2,512,48,48)
// ---------------------------------------------------------------------------

// Ping-pong scratch: max tensor is 2*64*384*384 floats = 18,874,368
__device__ float g_bufA[2u * 64u * 384u * 384u];
__device__ float g_bufB[2u * 64u * 384u * 384u];

// ---------------------------------------------------------------------------
// Tiled direct conv3x3 + bias + relu, NCHW, stride 1, SAME (zero pad).
// Block: 256 threads. Tile: 64 output channels x (8 x 16) pixels.
// Per-thread: 8 oc x 4 px register tile (pixels contiguous in x).
// cin processed in chunks of CHUNK (8, or 3 for the first layer).
// ---------------------------------------------------------------------------
template <int CIN, int COUT, int CHUNK>
__global__ void __launch_bounds__(256, 3)
conv3x3_bias_relu(const float* __restrict__ in,
                  const float* __restrict__ wgt,
                  const float* __restrict__ bias,
                  float* __restrict__ out,
                  int H, int W)
{
    static_assert(CIN % CHUNK == 0, "CIN divisible by CHUNK");
    constexpr int TH = 8;
    constexpr int TW = 16;
    constexpr int OCB = 64;            // output channels per block
    constexpr int WPAD = OCB + 1;      // smem pad to avoid STS bank conflicts

    __shared__ float wsm[CHUNK][9][WPAD];
    __shared__ float insm[CHUNK][TH + 2][TW + 2];

    const int tiles_x = W / TW;
    const int bx = (blockIdx.x % tiles_x) * TW;
    const int by = (blockIdx.x / tiles_x) * TH;
    const int n  = blockIdx.y;
    const int oc_base = blockIdx.z * OCB;

    const int tid = threadIdx.x;
    const int ocg = tid & 7;          // oc sub-block: oc = oc_base + ocg*8 + o
    const int pg  = tid >> 3;         // 0..31 pixel group
    const int row = pg >> 2;          // 0..7
    const int col = (pg & 3) * 4;     // 0,4,8,12

    float acc[8][4];
    #pragma unroll
    for (int o = 0; o < 8; ++o)
        #pragma unroll
        for (int p = 0; p < 4; ++p) acc[o][p] = 0.0f;

    #pragma unroll 1
    for (int c0 = 0; c0 < CIN; c0 += CHUNK) {
        // ---- load weight chunk: (OCB oc) x (CHUNK cin) x 9, coalesced in gmem
        {
            const float* wg = wgt + (size_t)oc_base * CIN * 9 + (size_t)c0 * 9;
            constexpr int PER_OC = CHUNK * 9;               // contiguous per oc
            constexpr int TOT = OCB * PER_OC;
            for (int idx = tid; idx < TOT; idx += 256) {
                int oc = idx / PER_OC;
                int r  = idx % PER_OC;                       // r = c*9 + k
                float v = wg[(size_t)oc * CIN * 9 + r];
                wsm[r / 9][r % 9][oc] = v;
            }
        }
        // ---- load input tile: CHUNK x (TH+2) x (TW+2), zero-padded borders
        {
            constexpr int ROWE = TW + 2;
            constexpr int TILE2D = (TH + 2) * ROWE;
            constexpr int TOT = CHUNK * TILE2D;
            for (int idx = tid; idx < TOT; idx += 256) {
                int c   = idx / TILE2D;
                int rem = idx % TILE2D;
                int iy  = rem / ROWE;
                int ix  = rem % ROWE;
                int gy = by + iy - 1;
                int gx = bx + ix - 1;
                float v = 0.0f;
                if (gy >= 0 && gy < H && gx >= 0 && gx < W)
                    v = in[(((size_t)n * CIN + c0 + c) * H + gy) * W + gx];
                insm[c][iy][ix] = v;
            }
        }
        __syncthreads();

        // ---- compute
        #pragma unroll 2
        for (int c = 0; c < CHUNK; ++c) {
            #pragma unroll
            for (int ky = 0; ky < 3; ++ky) {
                float iv[6];
                #pragma unroll
                for (int i = 0; i < 6; ++i)
                    iv[i] = insm[c][row + ky][col + i];
                #pragma unroll
                for (int kx = 0; kx < 3; ++kx) {
                    float wv[8];
                    #pragma unroll
                    for (int o = 0; o < 8; ++o)
                        wv[o] = wsm[c][ky * 3 + kx][ocg * 8 + o];
                    #pragma unroll
                    for (int o = 0; o < 8; ++o)
                        #pragma unroll
                        for (int p = 0; p < 4; ++p)
                            acc[o][p] = fmaf(wv[o], iv[kx + p], acc[o][p]);
                }
            }
        }
        __syncthreads();
    }

    // ---- epilogue: bias + relu, float4 stores (col aligned to 4)
    const int gy = by + row;
    const int gx = bx + col;
    #pragma unroll
    for (int o = 0; o < 8; ++o) {
        const int oc = oc_base + ocg * 8 + o;
        const float b = bias[oc];
        float4 v;
        v.x = fmaxf(acc[o][0] + b, 0.0f);
        v.y = fmaxf(acc[o][1] + b, 0.0f);
        v.z = fmaxf(acc[o][2] + b, 0.0f);
        v.w = fmaxf(acc[o][3] + b, 0.0f);
        float* dst = out + (((size_t)n * COUT + oc) * H + gy) * W + gx;
        *reinterpret_cast<float4*>(dst) = v;
    }
}

// ---------------------------------------------------------------------------
// 2x2 maxpool, NCHW. One thread per output element.
// ---------------------------------------------------------------------------
__global__ void maxpool2x2(const float* __restrict__ in,
                           float* __restrict__ out,
                           int total, int C, int Ho, int Wo)
{
    int idx = blockIdx.x * blockDim.x + threadIdx.x;
    if (idx >= total) return;
    int x = idx % Wo;
    int y = (idx / Wo) % Ho;
    int rest = idx / (Wo * Ho);          // rest = n*C + c
    const int Wi = 2 * Wo;
    const float* p = in + ((size_t)rest * (2 * Ho) + 2 * y) * Wi + 2 * x;
    float m = fmaxf(fmaxf(p[0], p[1]), fmaxf(p[Wi], p[Wi + 1]));
    out[idx] = m;
}

// ---------------------------------------------------------------------------
// Host-side launchers
// ---------------------------------------------------------------------------
template <int CIN, int COUT, int CHUNK>
static inline void launch_conv(const float* in, const float* w, const float* b,
                               float* out, int H, int W, int N)
{
    dim3 grid((W / 16) * (H / 8), N, COUT / 64);
    conv3x3_bias_relu<CIN, COUT, CHUNK><<<grid, 256>>>(in, w, b, out, H, W);
}

static inline void launch_pool(const float* in, float* out, int N, int C, int Hi, int Wi)
{
    int Ho = Hi / 2, Wo = Wi / 2;
    int total = N * C * Ho * Wo;
    maxpool2x2<<<(total + 255) / 256, 256>>>(in, out, total, C, Ho, Wo);
}

extern "C" void kernel_launch(void* const* d_in, const int* in_sizes, int n_in,
                              void* d_out, int out_size)
{
    (void)in_sizes; (void)n_in; (void)out_size;

    const float* x = (const float*)d_in[0];          // (2,3,384,384)
    // d_in[1] = pooling_mask (unused by reference)
    const float* w[11];
    const float* b[11];
    for (int k = 1; k <= 10; ++k) {
        w[k] = (const float*)d_in[2 + 2 * (k - 1)];
        b[k] = (const float*)d_in[3 + 2 * (k - 1)];
    }

    float* A;
    float* Bb;
    cudaGetSymbolAddress((void**)&A,  g_bufA);
    cudaGetSymbolAddress((void**)&Bb, g_bufB);
    float* O = (float*)d_out;
    const int N = 2;

    // Stage 1 @ 384x384
    launch_conv<3,   64, 3>(x,  w[1], b[1], A,  384, 384, N);
    launch_conv<64,  64, 8>(A,  w[2], b[2], Bb, 384, 384, N);
    launch_pool(Bb, A, N, 64, 384, 384);              // -> 192x192

    // Stage 2 @ 192x192
    launch_conv<64, 128, 8>(A,  w[3], b[3], Bb, 192, 192, N);
    launch_conv<128,128, 8>(Bb, w[4], b[4], A,  192, 192, N);
    launch_pool(A, Bb, N, 128, 192, 192);             // -> 96x96

    // Stage 3 @ 96x96
    launch_conv<128,256, 8>(Bb, w[5], b[5], A,  96, 96, N);
    launch_conv<256,256, 8>(A,  w[6], b[6], Bb, 96, 96, N);
    launch_conv<256,256, 8>(Bb, w[7], b[7], A,  96, 96, N);
    launch_pool(A, Bb, N, 256, 96, 96);               // -> 48x48

    // Stage 4 @ 48x48
    launch_conv<256,512, 8>(Bb, w[8],  b[8],  A,  48, 48, N);
    launch_conv<512,512, 8>(A,  w[9],  b[9],  Bb, 48, 48, N);
    launch_conv<512,512, 8>(Bb, w[10], b[10], O,  48, 48, N);
}